// round 16
// baseline (speedup 1.0000x reference)
#include <cuda_runtime.h>
#include <cstdint>

#define W 131072
#define J 21
#define NB 20
#define TILE 128
#define BLOCK 128
#define GRID (W / TILE)                    // 1024 blocks

// smem layout (floats), odd row strides -> conflict-free LDS
#define PSZ   ((TILE + 2) * 63)            // 8190 pose floats (frames base-1 .. base+TILE)
#define S_P2D 8192
#define P2DS  43                           // p2d row stride (42 padded)
#define S_LIFT (S_P2D + TILE * P2DS)       // 8192 + 5504 = 13696
#define LIFTS 61                           // lift row stride (60 padded)
#define S_CAM (S_LIFT + TILE * LIFTS)      // 13696 + 7808 = 21504
#define CAMS  7                            // cam row stride (6 padded)
#define SMEM_FLOATS (S_CAM + TILE * CAMS)  // 21504 + 896 = 22400
#define SMEM_BYTES (SMEM_FLOATS * 4)       // 89600 B

// weights folded with denominators
#define C_PROJ   (1.0f / 42.0f)
#define C_BONE   (1.0f / 20.0f)
#define C_SMOOTH (0.5f / 63.0f)
#define C_LIFT   (0.1f / 63.0f)

#define FULL 0xFFFFFFFFu

__device__ double g_acc;           // zero at load; last block resets each call
__device__ unsigned int g_count;   // wraps to 0 via atomicInc

__global__ __launch_bounds__(BLOCK)
void loss_kernel(const float* __restrict__ pose,   // [(W+1),3,J]
                 const float* __restrict__ cam,    // [W,2,3]
                 const float* __restrict__ p2d,    // [W,2,J]
                 const float* __restrict__ blen,   // [NB]
                 const float* __restrict__ lift,   // [W,3,NB]
                 const int*   __restrict__ bc,     // [NB,2]
                 const int*   __restrict__ lbc,    // [NB,2]
                 float* __restrict__ out)
{
    extern __shared__ float sm[];
    float* sp = sm;                 // pose tile, row stride 63 (frame slot 0 = base-1)
    float* sq = sm + S_P2D;         // p2d tile, row stride 43
    float* sl = sm + S_LIFT;        // lift tile, row stride 61
    float* sc = sm + S_CAM;         // cam tile, row stride 7

    __shared__ int   s_bc[2 * NB];
    __shared__ int   s_lbc[2 * NB];
    __shared__ float s_blen[NB];
    __shared__ float warp_sums[BLOCK / 32];
    __shared__ bool  is_last;

    const int tid  = threadIdx.x;
    const int base = blockIdx.x * TILE;

    // ---- tiny tables ----
    if (tid < 2 * NB)                s_bc[tid]        = bc[tid];
    else if (tid >= 64 && tid < 104) s_lbc[tid - 64]  = lbc[tid - 64];
    if (tid >= 104 && tid < 124)     s_blen[tid - 104] = blen[tid - 104];

    // ---- stage pose frames [base-1 .. base+TILE] (clamped at 0), coalesced ----
    {
        const int pstart = (base == 0) ? 0 : (base - 1);   // first staged frame
        const int off    = (base == 0) ? 63 : 0;           // slot shift when clamped
        const int pcount = ((base == 0) ? (TILE + 1) : (TILE + 2)) * 63;
        const float* g = pose + (size_t)pstart * 63;
        for (int i = tid; i < pcount; i += BLOCK)
            sp[off + i] = g[i];
    }
    // ---- stage p2d (42 -> stride 43) ----
    {
        const float* g = p2d + (size_t)base * 42;
        for (int i = tid; i < TILE * 42; i += BLOCK) {
            int f = i / 42, c = i - f * 42;
            sq[f * P2DS + c] = g[i];
        }
    }
    // ---- stage lift (60 -> stride 61) ----
    {
        const float* g = lift + (size_t)base * 60;
        for (int i = tid; i < TILE * 60; i += BLOCK) {
            int f = i / 60, c = i - f * 60;
            sl[f * LIFTS + c] = g[i];
        }
    }
    // ---- stage cam (6 -> stride 7) ----
    {
        const float* g = cam + (size_t)base * 6;
        for (int i = tid; i < TILE * 6; i += BLOCK) {
            int f = i / 6, c = i - f * 6;
            sc[f * CAMS + c] = g[i];
        }
    }
    __syncthreads();

    // connection tables identical? (uniform across threads -> no divergence)
    bool same_conn = true;
    #pragma unroll
    for (int i = 0; i < 2 * NB; i++) same_conn &= (s_bc[i] == s_lbc[i]);

    // ======== compute: thread t owns frame w = base + t ========
    const int w = base + tid;
    float acc = 0.0f;

    const float* P1 = sp + (tid + 2) * 63;   // pose frame w+1
    const float* P0 = P1 - 63;               // pose frame w
    const float* PM = P1 - 126;              // pose frame w-1
    const float* Q  = sq + tid * P2DS;
    const float* L  = sl + tid * LIFTS;
    const float* C  = sc + tid * CAMS;

    const float c0 = C[0], c1 = C[1], c2 = C[2];
    const float c3 = C[3], c4 = C[4], c5 = C[5];

    // ---- projection + smoothness, fused over joints ----
    if (w >= 1) {
        #pragma unroll
        for (int j = 0; j < J; j++) {
            float x = P1[j], y = P1[21 + j], z = P1[42 + j];
            float px = c0 * x + c1 * y + c2 * z - Q[j];
            float py = c3 * x + c4 * y + c5 * z - Q[21 + j];
            acc += C_PROJ * (px * px + py * py);
            float a0 = x - 2.0f * P0[j]      + PM[j];
            float a1 = y - 2.0f * P0[21 + j] + PM[21 + j];
            float a2 = z - 2.0f * P0[42 + j] + PM[42 + j];
            acc += C_SMOOTH * (a0 * a0 + a1 * a1 + a2 * a2);
        }
    } else {
        // w == 0: no smoothness; add the frame-0 bone term here
        #pragma unroll
        for (int j = 0; j < J; j++) {
            float x = P1[j], y = P1[21 + j], z = P1[42 + j];
            float px = c0 * x + c1 * y + c2 * z - Q[j];
            float py = c3 * x + c4 * y + c5 * z - Q[21 + j];
            acc += C_PROJ * (px * px + py * py);
        }
        const float* PZ = P0;   // pose frame 0
        #pragma unroll
        for (int b = 0; b < NB; b++) {
            int chb = s_bc[2 * b], pab = s_bc[2 * b + 1];
            float dx = PZ[chb]      - PZ[pab];
            float dy = PZ[21 + chb] - PZ[21 + pab];
            float dz = PZ[42 + chb] - PZ[42 + pab];
            float e = dx * dx + dy * dy + dz * dz - s_blen[b];
            acc += C_BONE * e * e;
        }
    }

    // ---- bone length + lift direction (frame w+1) ----
    #pragma unroll
    for (int b = 0; b < NB; b++) {
        const int chb = s_bc[2 * b], pab = s_bc[2 * b + 1];
        float bx = P1[chb]      - P1[pab];
        float by = P1[21 + chb] - P1[21 + pab];
        float bz = P1[42 + chb] - P1[42 + pab];
        float len = bx * bx + by * by + bz * bz;
        float e = len - s_blen[b];
        acc += C_BONE * e * e;

        float ux, uy, uz, n2;
        if (same_conn) {
            ux = bx; uy = by; uz = bz; n2 = len;
        } else {
            const int lc = s_lbc[2 * b], lp = s_lbc[2 * b + 1];
            ux = P1[lc]      - P1[lp];
            uy = P1[21 + lc] - P1[21 + lp];
            uz = P1[42 + lc] - P1[42 + lp];
            n2 = ux * ux + uy * uy + uz * uz;
        }
        float inv = 1.0f / sqrtf(n2);
        float ex = L[b]      - ux * inv;
        float ey = L[20 + b] - uy * inv;
        float ez = L[40 + b] - uz * inv;
        acc += C_LIFT * (ex * ex + ey * ey + ez * ez);
    }

    // ---- block reduction ----
    const int lane = tid & 31;
    const int wid  = tid >> 5;
    #pragma unroll
    for (int off = 16; off > 0; off >>= 1)
        acc += __shfl_down_sync(FULL, acc, off);
    if (lane == 0) warp_sums[wid] = acc;
    __syncthreads();

    if (wid == 0) {
        float v = (lane < BLOCK / 32) ? warp_sums[lane] : 0.0f;
        #pragma unroll
        for (int off = 2; off > 0; off >>= 1)
            v += __shfl_down_sync(FULL, v, off);
        if (lane == 0) {
            atomicAdd(&g_acc, (double)v);
            __threadfence();
            unsigned int ticket = atomicInc(&g_count, GRID - 1);
            is_last = (ticket == GRID - 1);
        }
    }
    __syncthreads();

    if (is_last && tid == 0) {
        __threadfence();
        out[0] = (float)g_acc;
        g_acc = 0.0;   // reset for next graph replay (g_count already wrapped)
        __threadfence();
    }
}

extern "C" void kernel_launch(void* const* d_in, const int* in_sizes, int n_in,
                              void* d_out, int out_size)
{
    const float* pose = (const float*)d_in[0];
    const float* cam  = (const float*)d_in[1];
    const float* p2d  = (const float*)d_in[2];
    const float* blen = (const float*)d_in[3];
    const float* lift = (const float*)d_in[4];
    const int*   bc   = (const int*)d_in[5];
    const int*   lbc  = (const int*)d_in[6];
    float* out = (float*)d_out;

    static bool attr_set = false;
    if (!attr_set) {
        cudaFuncSetAttribute(loss_kernel,
                             cudaFuncAttributeMaxDynamicSharedMemorySize,
                             SMEM_BYTES);
        attr_set = true;
    }

    loss_kernel<<<GRID, BLOCK, SMEM_BYTES>>>(pose, cam, p2d, blen, lift, bc, lbc, out);
}

// round 17
// speedup vs baseline: 2.5403x; 2.5403x over previous
#include <cuda_runtime.h>
#include <cstdint>

#define W 131072
#define J 21
#define NB 20
#define BLOCK 256
#define GRID 1024
#define WPB (BLOCK / 32)
#define NWARP (GRID * WPB)                 // 8192 warps
#define CHUNK (W / NWARP)                  // 16 frames per warp (exact)
#define NSTEP (CHUNK / 2)                  // 8 steps of 2 frames
#define NSTAGE 4

#define WBUF 356                            // floats per warp-stage (padded)
// stage layout (floats):
//   [0..119]   lift frames wn, wn+1        (byte 0,    16B-aligned)
//   [120..131] cam  frames wn, wn+1        (byte 480)
//   [132..215] p2d  frames wn, wn+1        (byte 528)
//   [216..341] pose frames wn+1, wn+2      (byte 864)

// weights folded with denominators
#define C_PROJ   (1.0f / 42.0f)
#define C_BONE   (1.0f / 20.0f)
#define C_SMOOTH (0.5f / 63.0f)
#define C_LIFT   (0.1f / 63.0f)

#define FULL 0xFFFFFFFFu

__device__ double g_acc;           // zero at load; last block resets each call
__device__ unsigned int g_count;   // wraps to 0 via atomicInc

__device__ __forceinline__ void cp4(uint32_t dst, const float* src) {
    asm volatile("cp.async.ca.shared.global [%0], [%1], 4;" :: "r"(dst), "l"(src));
}
__device__ __forceinline__ void cp16(uint32_t dst, const float* src) {
    asm volatile("cp.async.cg.shared.global [%0], [%1], 16;" :: "r"(dst), "l"(src));
}
#define CP_COMMIT() asm volatile("cp.async.commit_group;" ::: "memory")
#define CP_WAIT2()  asm volatile("cp.async.wait_group 2;" ::: "memory")

__device__ __forceinline__ void issue_step(uint32_t sb, int wid, int lane, int stage, int wn,
                                           const float* __restrict__ pose,
                                           const float* __restrict__ cam,
                                           const float* __restrict__ p2d,
                                           const float* __restrict__ lift)
{
    uint32_t b = sb + (uint32_t)((stage * WPB + wid) * WBUF) * 4u;
    // lift: 120 floats, 16B-aligned (wn even)
    if (lane < 30) cp16(b + lane * 16u, lift + (size_t)wn * 60 + lane * 4);
    // cam: 12 floats
    if (lane < 3)  cp16(b + 480u + lane * 16u, cam + (size_t)wn * 6 + lane * 4);
    // p2d: 84 floats
    if (lane < 21) cp16(b + 528u + lane * 16u, p2d + (size_t)wn * 42 + lane * 4);
    // pose: 126 floats at odd float offset -> 4B copies
    const float* ps = pose + (size_t)(wn + 1) * 63;
    cp4(b + 864u + lane * 4u, ps + lane);
    cp4(b + 864u + 128u + lane * 4u, ps + 32 + lane);
    cp4(b + 864u + 256u + lane * 4u, ps + 64 + lane);
    if (lane < 30) cp4(b + 864u + 384u + lane * 4u, ps + 96 + lane);
}

__global__ __launch_bounds__(BLOCK)
void loss_kernel(const float* __restrict__ pose,   // [(W+1),3,J]
                 const float* __restrict__ cam,    // [W,2,3]
                 const float* __restrict__ p2d,    // [W,2,J]
                 const float* __restrict__ blen,   // [NB]
                 const float* __restrict__ lift,   // [W,3,NB]
                 const int*   __restrict__ bc,     // [NB,2]
                 const int*   __restrict__ lbc,    // [NB,2]
                 float* __restrict__ out)
{
    __shared__ __align__(16) float smf[NSTAGE * WPB * WBUF];

    const int tid  = threadIdx.x;
    const int lane = tid & 31;
    const int wid  = tid >> 5;
    const int gw   = blockIdx.x * WPB + wid;
    const int f0   = gw * CHUNK;

    const bool jok = lane < J;
    const bool bok = lane < NB;

    uint32_t sb = (uint32_t)__cvta_generic_to_shared(smf);

    int ch = 0, pa = 0, lch = 0, lpa = 0;
    float bl = 0.0f;
    if (bok) {
        ch  = bc[2 * lane];
        pa  = bc[2 * lane + 1];
        lch = lbc[2 * lane];
        lpa = lbc[2 * lane + 1];
        bl  = blen[lane];
    }
    const bool same_conn = __all_sync(FULL, !bok || (lch == ch && lpa == pa));

    float acc = 0.0f;

    // ---- prologue: issue steps 0,1,2 into stages 0,1,2 ----
    issue_step(sb, wid, lane, 0, f0,     pose, cam, p2d, lift); CP_COMMIT();
    issue_step(sb, wid, lane, 1, f0 + 2, pose, cam, p2d, lift); CP_COMMIT();
    issue_step(sb, wid, lane, 2, f0 + 4, pose, cam, p2d, lift); CP_COMMIT();

    // ---- lead-in history: x0 = frame f0, xm = frame max(f0-1,0) ----
    const float* pA = pose + (size_t)f0 * 63;
    float x0 = jok ? pA[lane]          : 0.0f;
    float y0 = jok ? pA[J + lane]      : 0.0f;
    float z0 = jok ? pA[2 * J + lane]  : 0.0f;
    const float* pB = pose + (size_t)(f0 > 0 ? f0 - 1 : 0) * 63;
    float xm = jok ? pB[lane]          : 0.0f;
    float ym = jok ? pB[J + lane]      : 0.0f;
    float zm = jok ? pB[2 * J + lane]  : 0.0f;

    // frame-0 bone term (done once, by the warp owning frame 0)
    if (f0 == 0) {
        float dx = __shfl_sync(FULL, x0, ch) - __shfl_sync(FULL, x0, pa);
        float dy = __shfl_sync(FULL, y0, ch) - __shfl_sync(FULL, y0, pa);
        float dz = __shfl_sync(FULL, z0, ch) - __shfl_sync(FULL, z0, pa);
        float len = dx * dx + dy * dy + dz * dz;
        float e = len - bl;
        if (bok) acc += C_BONE * e * e;
    }

    #pragma unroll
    for (int s = 0; s < NSTEP; s++) {
        const int w = f0 + 2 * s;

        // wait for step s's stage (<=2 newer groups pending), make visible warp-wide
        CP_WAIT2();
        __syncwarp();

        const float* cur = smf + ((s & 3) * WPB + wid) * WBUF;

        const float x1 = cur[216 + lane];
        const float y1 = cur[237 + lane];
        const float z1 = cur[258 + lane];
        const float x2 = cur[279 + lane];
        const float y2 = cur[300 + lane];
        const float z2 = cur[321 + lane];

        // ---- frame w ----
        {
            float c0 = cur[120], c1 = cur[121], c2 = cur[122];
            float c3 = cur[123], c4 = cur[124], c5 = cur[125];
            float px = c0 * x1 + c1 * y1 + c2 * z1 - cur[132 + lane];
            float py = c3 * x1 + c4 * y1 + c5 * z1 - cur[153 + lane];
            if (jok) acc += C_PROJ * (px * px + py * py);

            if (w >= 1 || s > 0) {
                float a0 = x1 - 2.0f * x0 + xm;
                float a1 = y1 - 2.0f * y0 + ym;
                float a2 = z1 - 2.0f * z0 + zm;
                if (jok) acc += C_SMOOTH * (a0 * a0 + a1 * a1 + a2 * a2);
            }

            float bx = __shfl_sync(FULL, x1, ch) - __shfl_sync(FULL, x1, pa);
            float by = __shfl_sync(FULL, y1, ch) - __shfl_sync(FULL, y1, pa);
            float bz = __shfl_sync(FULL, z1, ch) - __shfl_sync(FULL, z1, pa);
            float len = bx * bx + by * by + bz * bz;
            float e = len - bl;
            if (bok) acc += C_BONE * e * e;

            float ux, uy, uz;
            if (same_conn) { ux = bx; uy = by; uz = bz; }
            else {
                ux = __shfl_sync(FULL, x1, lch) - __shfl_sync(FULL, x1, lpa);
                uy = __shfl_sync(FULL, y1, lch) - __shfl_sync(FULL, y1, lpa);
                uz = __shfl_sync(FULL, z1, lch) - __shfl_sync(FULL, z1, lpa);
            }
            float inv = bok ? (1.0f / sqrtf(ux * ux + uy * uy + uz * uz)) : 0.0f;
            float ex = cur[lane]      - ux * inv;
            float ey = cur[20 + lane] - uy * inv;
            float ez = cur[40 + lane] - uz * inv;
            if (bok) acc += C_LIFT * (ex * ex + ey * ey + ez * ez);
        }

        // ---- frame w+1 ----
        {
            float c0 = cur[126], c1 = cur[127], c2 = cur[128];
            float c3 = cur[129], c4 = cur[130], c5 = cur[131];
            float px = c0 * x2 + c1 * y2 + c2 * z2 - cur[174 + lane];
            float py = c3 * x2 + c4 * y2 + c5 * z2 - cur[195 + lane];
            if (jok) acc += C_PROJ * (px * px + py * py);

            float a0 = x2 - 2.0f * x1 + x0;
            float a1 = y2 - 2.0f * y1 + y0;
            float a2 = z2 - 2.0f * z1 + z0;
            if (jok) acc += C_SMOOTH * (a0 * a0 + a1 * a1 + a2 * a2);

            float bx = __shfl_sync(FULL, x2, ch) - __shfl_sync(FULL, x2, pa);
            float by = __shfl_sync(FULL, y2, ch) - __shfl_sync(FULL, y2, pa);
            float bz = __shfl_sync(FULL, z2, ch) - __shfl_sync(FULL, z2, pa);
            float len = bx * bx + by * by + bz * bz;
            float e = len - bl;
            if (bok) acc += C_BONE * e * e;

            float ux, uy, uz;
            if (same_conn) { ux = bx; uy = by; uz = bz; }
            else {
                ux = __shfl_sync(FULL, x2, lch) - __shfl_sync(FULL, x2, lpa);
                uy = __shfl_sync(FULL, y2, lch) - __shfl_sync(FULL, y2, lpa);
                uz = __shfl_sync(FULL, z2, lch) - __shfl_sync(FULL, z2, lpa);
            }
            float inv = bok ? (1.0f / sqrtf(ux * ux + uy * uy + uz * uz)) : 0.0f;
            float ex = cur[60 + lane]  - ux * inv;
            float ey = cur[80 + lane]  - uy * inv;
            float ez = cur[100 + lane] - uz * inv;
            if (bok) acc += C_LIFT * (ex * ex + ey * ey + ez * ez);
        }

        // ---- issue step s+3 into stage (s+3)&3 (overwrites step s-1's stage) ----
        if (s + 3 < NSTEP)
            issue_step(sb, wid, lane, (s + 3) & 3, f0 + 2 * (s + 3), pose, cam, p2d, lift);
        CP_COMMIT();   // always commit (possibly empty) to keep group counts aligned

        // rotate history: prev = pose[w+1], cur = pose[w+2]
        xm = x1; ym = y1; zm = z1;
        x0 = x2; y0 = y2; z0 = z2;
    }

    // ---- warp reduction ----
    #pragma unroll
    for (int off = 16; off > 0; off >>= 1)
        acc += __shfl_down_sync(FULL, acc, off);

    __shared__ float warp_sums[WPB];
    __shared__ bool  is_last;
    if (lane == 0) warp_sums[wid] = acc;
    __syncthreads();

    if (wid == 0) {
        float v = (lane < WPB) ? warp_sums[lane] : 0.0f;
        #pragma unroll
        for (int off = 4; off > 0; off >>= 1)
            v += __shfl_down_sync(FULL, v, off);
        if (lane == 0) {
            atomicAdd(&g_acc, (double)v);
            __threadfence();
            unsigned int ticket = atomicInc(&g_count, GRID - 1);
            is_last = (ticket == GRID - 1);
        }
    }
    __syncthreads();

    if (is_last && tid == 0) {
        __threadfence();
        out[0] = (float)g_acc;
        g_acc = 0.0;   // reset for next graph replay (g_count already wrapped)
        __threadfence();
    }
}

extern "C" void kernel_launch(void* const* d_in, const int* in_sizes, int n_in,
                              void* d_out, int out_size)
{
    const float* pose = (const float*)d_in[0];
    const float* cam  = (const float*)d_in[1];
    const float* p2d  = (const float*)d_in[2];
    const float* blen = (const float*)d_in[3];
    const float* lift = (const float*)d_in[4];
    const int*   bc   = (const int*)d_in[5];
    const int*   lbc  = (const int*)d_in[6];
    float* out = (float*)d_out;

    loss_kernel<<<GRID, BLOCK>>>(pose, cam, p2d, blen, lift, bc, lbc, out);
}